// round 2
// baseline (speedup 1.0000x reference)
#include <cuda_runtime.h>

// CRF loss, fully warp-synchronous: one 32-thread CTA per batch row.
// Scaled forward algorithm in probability domain:
//   P_{t+1}[j] = (sum_i P_t[i] * E[i][j]) * exp(f_t[j]),  E = exp(trans)
// P lives in registers (lane l owns columns l and l+32), gathered per step
// with 50 warp shuffles. Exact power-of-2 rescaling every step using the
// exponent of P[1] (free: it's already shuffled), accumulated in an int.
// No shared memory, no __syncthreads anywhere in the recurrence.

constexpr int TT = 50;
constexpr int LL = 256;
constexpr int STARTT = TT - 2;
constexpr int STOPT  = TT - 1;

#define LOG2E 1.4426950408889634f
#define LN2F  0.6931471805599453f

__device__ float    g_partial[1024];
__device__ unsigned g_done = 0;

__device__ __forceinline__ float ex2(float x) {
    float r;
    asm("ex2.approx.ftz.f32 %0, %1;" : "=f"(r) : "f"(x));
    return r;
}

__global__ void __launch_bounds__(32)
crf_kernel(const float* __restrict__ feats, const float* __restrict__ trans,
           const int* __restrict__ tags, const int* __restrict__ mask,
           float* __restrict__ out) {
    const int b    = blockIdx.x;
    const int lane = threadIdx.x;
    const int j0   = lane;
    const int j1   = lane + 32;
    const bool j1v = (j1 < TT);
    const int j1c  = j1v ? j1 : (TT - 1);

    // ---- sequence length: count of nonzero mask (mask is a prefix) ----
    int len = 0;
#pragma unroll
    for (int c = 0; c < 8; c++) {
        int m = mask[b * LL + c * 32 + lane];
        len += __popc(__ballot_sync(0xffffffffu, m != 0));
    }

    // ---- E columns in registers: E0[i] = exp(trans[i][j0]), E1 for j1 ----
    float E0[TT], E1[TT];
#pragma unroll
    for (int i = 0; i < TT; i++) {
        E0[i] = ex2(trans[i * TT + j0] * LOG2E);
        float e1 = ex2(trans[i * TT + j1c] * LOG2E);
        E1[i] = j1v ? e1 : 0.f;
    }

    const float* fb = feats + (size_t)b * LL * TT;

    // ---- init: part0 = feats[:,0,:] + trans[START,:] ----
    // trans[START,:] is the constant NEG mask row; subtract s0 = trans[START,1]
    // exactly so p stays in range, track scale in C2f.
    const float s0 = trans[STARTT * TT + 1];
    float p0 = ex2((fb[j0] + trans[STARTT * TT + j0] - s0) * LOG2E);
    float p1 = j1v ? ex2((fb[j1c] + trans[STARTT * TT + j1c] - s0) * LOG2E) : 0.f;
    const float C2f = s0 * LOG2E;
    int C2k = 0;

    // ---- distance-2 feats prefetch ----
    float fc0 = 0.f, fc1 = 0.f, fn0 = 0.f, fn1 = 0.f;
    if (len > 1) { fc0 = fb[TT + j0]; fc1 = fb[TT + j1c]; }
    if (len > 2) { fn0 = fb[2 * TT + j0]; fn1 = fb[2 * TT + j1c]; }

    for (int t = 1; t < len; ++t) {
        const float f0 = fc0, f1 = fc1;
        fc0 = fn0; fc1 = fn1;
        if (t + 2 < len) {
            fn0 = fb[(t + 2) * TT + j0];
            fn1 = fb[(t + 2) * TT + j1c];
        }

        float a0 = 0.f, a1 = 0.f, a2 = 0.f, a3 = 0.f;
        float c0 = 0.f, c1 = 0.f, c2 = 0.f, c3 = 0.f;
        float v1 = 0.f;
#pragma unroll
        for (int i = 0; i < 32; i++) {
            float v = __shfl_sync(0xffffffffu, p0, i);
            if (i == 1) v1 = v;
            switch (i & 3) {
                case 0: a0 = fmaf(v, E0[i], a0); c0 = fmaf(v, E1[i], c0); break;
                case 1: a1 = fmaf(v, E0[i], a1); c1 = fmaf(v, E1[i], c1); break;
                case 2: a2 = fmaf(v, E0[i], a2); c2 = fmaf(v, E1[i], c2); break;
                case 3: a3 = fmaf(v, E0[i], a3); c3 = fmaf(v, E1[i], c3); break;
            }
        }
#pragma unroll
        for (int i = 32; i < TT; i++) {
            float v = __shfl_sync(0xffffffffu, p1, i - 32);
            switch (i & 3) {
                case 0: a0 = fmaf(v, E0[i], a0); c0 = fmaf(v, E1[i], c0); break;
                case 1: a1 = fmaf(v, E0[i], a1); c1 = fmaf(v, E1[i], c1); break;
                case 2: a2 = fmaf(v, E0[i], a2); c2 = fmaf(v, E1[i], c2); break;
                case 3: a3 = fmaf(v, E0[i], a3); c3 = fmaf(v, E1[i], c3); break;
            }
        }

        // exact pow-2 rescale using P[1]'s exponent (no reduction needed)
        int k = (__float_as_int(v1) >> 23) - 127;
        float sc = __int_as_float((127 - k) << 23);
        C2k += k;

        float acc0 = ((a0 + a1) + (a2 + a3)) * sc;
        float acc1 = ((c0 + c1) + (c2 + c3)) * sc;
        p0 = acc0 * ex2(f0 * LOG2E);
        p1 = acc1 * ex2(f1 * LOG2E);
    }

    // ---- terminal: logsumexp_i(part[i] + trans[i,STOP]) ----
    const float tref = trans[1 * TT + STOPT];
    float w0 = ex2((trans[j0 * TT + STOPT] - tref) * LOG2E);
    float w1 = j1v ? ex2((trans[j1c * TT + STOPT] - tref) * LOG2E) : 0.f;
    float s = p0 * w0 + p1 * w1;
#pragma unroll
    for (int o = 16; o; o >>= 1) s += __shfl_xor_sync(0xffffffffu, s, o);
    float fwd = (log2f(s) + C2f + (float)C2k) * LN2F + tref;

    // ---- gold score ----
    const int* tgb = tags + b * LL;
    float gl = 0.f;
#pragma unroll 4
    for (int t = lane; t < len; t += 32) {
        int tg = tgb[t];
        int pv = (t == 0) ? STARTT : tgb[t - 1];
        gl += fb[t * TT + tg] + trans[pv * TT + tg];
    }
#pragma unroll
    for (int o = 16; o; o >>= 1) gl += __shfl_xor_sync(0xffffffffu, gl, o);

    if (lane == 0) {
        float gold = gl + trans[tgb[len - 1] * TT + STOPT];
        g_partial[b] = fwd - gold;
    }

    // ---- fused finalize: last block sums all partials (fixed order) ----
    __threadfence();
    unsigned rank = 0;
    if (lane == 0) rank = atomicAdd(&g_done, 1u);
    rank = __shfl_sync(0xffffffffu, rank, 0);
    if (rank == gridDim.x - 1) {
        const int B = gridDim.x;
        float acc = 0.f;
        for (int i = lane; i < B; i += 32) {
            float v;
            asm volatile("ld.global.cg.f32 %0, [%1];" : "=f"(v)
                         : "l"(&g_partial[i]));
            acc += v;
        }
#pragma unroll
        for (int o = 16; o; o >>= 1) acc += __shfl_xor_sync(0xffffffffu, acc, o);
        if (lane == 0) {
            *out = acc;
            g_done = 0;   // reset for next graph replay
        }
    }
}

extern "C" void kernel_launch(void* const* d_in, const int* in_sizes, int n_in,
                              void* d_out, int out_size) {
    const float* feats = (const float*)d_in[0];
    const float* trans = (const float*)d_in[1];
    const int*   tags  = (const int*)d_in[2];
    const int*   mask  = (const int*)d_in[3];
    int B = in_sizes[0] / (LL * TT);

    crf_kernel<<<B, 32>>>(feats, trans, tags, mask, (float*)d_out);
}

// round 3
// speedup vs baseline: 1.9206x; 1.9206x over previous
#include <cuda_runtime.h>

// CRF loss. One 64-thread CTA per batch row; thread j owns output column j.
// Scaled forward algorithm in probability domain:
//   P_{t+1}[j] = (sum_i P_t[i] * E[i][j]) * exp(f_t[j]),  E = exp(trans)
// E column in registers (50 regs/thread, no spill), P ping-pongs in shared
// (13 LDS.128 per step). Exact power-of-2 rescaling every step using the
// exponent of max(P[1..3]) from the first float4 — no reductions in the loop,
// one __syncthreads per step. ex2 via raw asm, off the critical path.

constexpr int TT = 50;    // tags
constexpr int TP = 52;    // padded to 13 float4
constexpr int LL = 256;   // max length
constexpr int NTH = 64;
constexpr int STARTT = TT - 2;
constexpr int STOPT  = TT - 1;

#define LOG2E 1.4426950408889634f
#define LN2F  0.6931471805599453f

__device__ float    g_partial[1024];
__device__ unsigned g_done = 0;

__device__ __forceinline__ float ex2(float x) {
    float r;
    asm("ex2.approx.ftz.f32 %0, %1;" : "=f"(r) : "f"(x));
    return r;
}

__device__ __forceinline__ float blockSum64(float v, volatile float* red) {
#pragma unroll
    for (int o = 16; o; o >>= 1) v += __shfl_xor_sync(0xffffffffu, v, o);
    if ((threadIdx.x & 31) == 0) red[threadIdx.x >> 5] = v;
    __syncthreads();
    v = red[0] + red[1];
    __syncthreads();
    return v;
}

__global__ void __launch_bounds__(NTH, 1)
crf_kernel(const float* __restrict__ feats, const float* __restrict__ trans,
           const int* __restrict__ tags, const int* __restrict__ mask,
           float* __restrict__ out) {
    __shared__ __align__(16) float Pb[2][TP];
    __shared__ float red[2];
    __shared__ int s_len;
    __shared__ unsigned s_rank;

    const int b   = blockIdx.x;
    const int tid = threadIdx.x;
    const int j   = tid;
    const bool jv = (j < TT);
    const int jc  = jv ? j : (TT - 1);

    if (tid == 0) s_len = 0;
    __syncthreads();

    // ---- sequence length (mask is a 0/1 prefix) ----
    {
        const int4* m4 = (const int4*)(mask + (size_t)b * LL);
        int4 v = m4[tid];
        int c = (v.x != 0) + (v.y != 0) + (v.z != 0) + (v.w != 0);
#pragma unroll
        for (int o = 16; o; o >>= 1) c += __shfl_xor_sync(0xffffffffu, c, o);
        if ((tid & 31) == 0) atomicAdd(&s_len, c);
    }

    // ---- E[:,j] = exp(trans[:,j]) in registers ----
    float E[TP];
#pragma unroll
    for (int i = 0; i < TT; i++) {
        float e = ex2(trans[i * TT + jc] * LOG2E);
        E[i] = jv ? e : 0.f;
    }
    E[50] = 0.f; E[51] = 0.f;

    const float* fb = feats + (size_t)b * LL * TT;

    // ---- init: part0 = feats[:,0,:] + trans[START,:], offset by s0 ----
    const float s0 = trans[STARTT * TT + 1];
    {
        float p = 0.f;
        if (jv) p = ex2((fb[jc] + trans[STARTT * TT + jc] - s0) * LOG2E);
        if (j < TP) Pb[0][j] = jv ? p : 0.f;
    }
    float C2f = s0 * LOG2E;
    int   C2k = 0;
    __syncthreads();
    const int len = s_len;

    // ---- distance-2 feats prefetch ----
    float fc = 0.f, fn = 0.f;
    if (len > 1) fc = fb[TT + jc];
    if (len > 2) fn = fb[2 * TT + jc];

    int cur = 0;
    for (int t = 1; t < len; ++t) {
        float ef = ex2(fc * LOG2E);           // independent of P: off the chain
        fc = fn;
        if (t + 2 < len) fn = fb[(t + 2) * TT + jc];

        const float4* p4 = (const float4*)Pb[cur];
        float4 v0 = p4[0];
        // exact pow-2 rescale pivot from P[1..3] (real tags, > 0)
        float m = fmaxf(fmaxf(v0.y, v0.z), v0.w);
        int   k = (__float_as_int(m) >> 23) - 127;
        float sc = __int_as_float((127 - k) << 23);

        float a0 = v0.x * E[0], a1 = v0.y * E[1];
        float a2 = v0.z * E[2], a3 = v0.w * E[3];
        float b0 = 0.f, b1 = 0.f, b2 = 0.f, b3 = 0.f;
#pragma unroll
        for (int q = 1; q < 13; q += 2) {
            float4 v = p4[q];
            a0 = fmaf(v.x, E[4 * q + 0], a0);
            a1 = fmaf(v.y, E[4 * q + 1], a1);
            a2 = fmaf(v.z, E[4 * q + 2], a2);
            a3 = fmaf(v.w, E[4 * q + 3], a3);
        }
#pragma unroll
        for (int q = 2; q < 13; q += 2) {
            float4 v = p4[q];
            b0 = fmaf(v.x, E[4 * q + 0], b0);
            b1 = fmaf(v.y, E[4 * q + 1], b1);
            b2 = fmaf(v.z, E[4 * q + 2], b2);
            b3 = fmaf(v.w, E[4 * q + 3], b3);
        }
        float acc = ((a0 + b0) + (a1 + b1)) + ((a2 + b2) + (a3 + b3));
        float p = acc * sc * ef;
        C2k += k;

        if (j < TP) Pb[cur ^ 1][j] = jv ? p : 0.f;
        __syncthreads();
        cur ^= 1;
    }

    // ---- terminal: logsumexp_i(part[i] + trans[i, STOP]) ----
    const float tref = trans[1 * TT + STOPT];
    float s = 0.f;
    if (jv) {
        float w = ex2((trans[jc * TT + STOPT] - tref) * LOG2E);
        s = Pb[cur][j] * w;
    }
    float sumv = blockSum64(s, red);
    float fwd = (log2f(sumv) + C2f + (float)C2k) * LN2F + tref;

    // ---- gold score ----
    const int* tgb = tags + (size_t)b * LL;
    float gl = 0.f;
    for (int t = tid; t < len; t += NTH) {
        int tg = tgb[t];
        int pv = (t == 0) ? STARTT : tgb[t - 1];
        gl += fb[t * TT + tg] + trans[pv * TT + tg];
    }
    float gold = blockSum64(gl, red);

    if (tid == 0) {
        gold += trans[tgb[len - 1] * TT + STOPT];
        g_partial[b] = fwd - gold;
    }

    // ---- fused finalize: last CTA sums all partials (fixed order) ----
    __threadfence();
    if (tid == 0) s_rank = atomicAdd(&g_done, 1u);
    __syncthreads();
    if (s_rank == gridDim.x - 1) {
        const int B = gridDim.x;
        if (tid < 32) {
            float acc = 0.f;
            for (int i = tid; i < B; i += 32) {
                float v;
                asm volatile("ld.global.cg.f32 %0, [%1];" : "=f"(v)
                             : "l"(&g_partial[i]));
                acc += v;
            }
#pragma unroll
            for (int o = 16; o; o >>= 1)
                acc += __shfl_xor_sync(0xffffffffu, acc, o);
            if (tid == 0) {
                *out = acc;
                g_done = 0;   // reset for next graph replay
            }
        }
    }
}

extern "C" void kernel_launch(void* const* d_in, const int* in_sizes, int n_in,
                              void* d_out, int out_size) {
    const float* feats = (const float*)d_in[0];
    const float* trans = (const float*)d_in[1];
    const int*   tags  = (const int*)d_in[2];
    const int*   mask  = (const int*)d_in[3];
    int B = in_sizes[0] / (LL * TT);

    crf_kernel<<<B, NTH>>>(feats, trans, tags, mask, (float*)d_out);
}